// round 14
// baseline (speedup 1.0000x reference)
#include <cuda_runtime.h>
#include <cuda_bf16.h>
#include <math.h>
#include <stdint.h>

#define B_SZ 4
#define L_SEQ 2048
#define D_MODEL 258
#define N_LAYERS 4
#define D_STATE 16
#define D_INNER 516
#define DT_RANK 17
#define TWO_DI 1032
#define XW 56            // padded xdbl stride (49 real cols)
#define NTOK 8192
#define EPS 1e-5f
#define KM 288           // 258 padded to 32-chunks
#define KI 544           // 516 padded
#define WIN_R 1152       // 9 * 128
#define WOUT_R 320       // 5 * 64
#define WXP_R 64
#define NCHK 128         // scan chunks
#define SCT 16           // tokens per scan chunk

typedef __nv_bfloat16 bf16;

// -------- device scratch (zero-init; +pad for vectorized edge reads) --------
__device__ __align__(256) float g_x[NTOK * D_MODEL];
__device__ __align__(256) bf16  g_xn[NTOK * KM];
__device__ __align__(256) bf16  g_xz[NTOK * TWO_DI + 256];
__device__ __align__(256) bf16  g_xc[NTOK * KI + 256];
__device__ __align__(256) float g_xdbl[NTOK * XW];
__device__ __align__(256) bf16  g_y2[NTOK * KI + 256];
__device__ __align__(256) bf16  g_win[N_LAYERS * WIN_R * KM];
__device__ __align__(256) bf16  g_wout[N_LAYERS * WOUT_R * KI];
__device__ __align__(256) bf16  g_wxp[N_LAYERS * WXP_R * KI];
__device__ __align__(256) float g_L[B_SZ * NCHK * D_INNER * D_STATE];
__device__ __align__(256) float g_H0[B_SZ * NCHK * D_INNER * D_STATE];
__device__ __align__(256) float g_sdt[B_SZ * NCHK * D_INNER];

// -------- helpers --------
__device__ __forceinline__ uint32_t smem_u32(const void* p) {
    uint32_t a;
    asm("{ .reg .u64 t; cvta.to.shared.u64 t, %1; cvt.u32.u64 %0, t; }" : "=r"(a) : "l"(p));
    return a;
}
__device__ __forceinline__ void cp_async16(uint32_t dst, const void* src) {
    asm volatile("cp.async.cg.shared.global [%0], [%1], 16;" :: "r"(dst), "l"(src));
}
#define CP_COMMIT() asm volatile("cp.async.commit_group;" ::: "memory")

__device__ __forceinline__ void mma_bf16(float* d, const uint32_t* a, const uint32_t* b) {
    asm volatile(
        "mma.sync.aligned.m16n8k16.row.col.f32.bf16.bf16.f32 "
        "{%0,%1,%2,%3},{%4,%5,%6,%7},{%8,%9},{%0,%1,%2,%3};"
        : "+f"(d[0]), "+f"(d[1]), "+f"(d[2]), "+f"(d[3])
        : "r"(a[0]), "r"(a[1]), "r"(a[2]), "r"(a[3]), "r"(b[0]), "r"(b[1]));
}
__device__ __forceinline__ void ldsm_x4(uint32_t* r, uint32_t addr) {
    asm volatile("ldmatrix.sync.aligned.m8n8.x4.shared.b16 {%0,%1,%2,%3}, [%4];"
        : "=r"(r[0]), "=r"(r[1]), "=r"(r[2]), "=r"(r[3]) : "r"(addr));
}
__device__ __forceinline__ void ldsm_x2(uint32_t* r, uint32_t addr) {
    asm volatile("ldmatrix.sync.aligned.m8n8.x2.shared.b16 {%0,%1}, [%2];"
        : "=r"(r[0]), "=r"(r[1]) : "r"(addr));
}

// -------- bf16 mma GEMM: C[8192,N] = A[8192,K]bf16 @ W[N,K]bf16^T --------
#define AW 20            // smem row stride in words (40 bf16) — LDSM conflict-free
template <int BM, int BN, int OUTMODE, int NSTAGE>
__global__ __launch_bounds__(256) void gemm_bf16(
    const bf16* __restrict__ A, const bf16* __restrict__ W,
    void* __restrict__ Cv, int N_store, int K, int lda, int ldc) {
    constexpr int MW = BM / 32;
    constexpr int NW = 8 / MW;
    constexpr int WN = BN / NW;
    constexpr int NT = WN / 8;
    constexpr int ASTG = BM * AW, BSTG = BN * AW, STG = ASTG + BSTG;
    extern __shared__ uint32_t sm[];
    const int tid = threadIdx.x, wid = tid >> 5, lane = tid & 31;
    const int warpM = wid % MW, warpN = wid / MW;
    const int quad = lane >> 2, qk = lane & 3;
    const int bm = blockIdx.y * BM, bn = blockIdx.x * BN;
    float acc[2][NT][4];
    #pragma unroll
    for (int i = 0; i < 2; ++i)
        #pragma unroll
        for (int j = 0; j < NT; ++j)
            #pragma unroll
            for (int k = 0; k < 4; ++k) acc[i][j][k] = 0.f;

    const bf16* Ab = A + (size_t)bm * lda;
    const bf16* Wb = W + (size_t)bn * K;
    const int nch = K >> 5;
    const uint32_t sm_u = smem_u32(sm);
    const int l8 = lane & 7, jm = lane >> 3;

    const uint32_t aLM = sm_u +
        (uint32_t)(((warpM * 32 + ((jm & 1) << 3) + l8) * AW + ((jm >> 1) << 2)) * 4);
    const uint32_t bLM4 = sm_u + ASTG * 4 +
        (uint32_t)(((warpN * WN + ((jm >> 1) << 3) + l8) * AW + ((jm & 1) << 2)) * 4);
    const uint32_t bLM2 = sm_u + ASTG * 4 +
        (uint32_t)(((warpN * WN + l8) * AW + (((lane >> 3) & 1) << 2)) * 4);

    auto load_chunk = [&](int c, int st) {
        const bf16* Ac = Ab + c * 32;
        #pragma unroll
        for (int fi = tid; fi < BM * 4; fi += 256) {
            int r = fi >> 2, sg = fi & 3;
            cp_async16(sm_u + (uint32_t)(st * STG + r * AW + sg * 4) * 4,
                       Ac + (size_t)r * lda + sg * 8);
        }
        const bf16* Wc = Wb + c * 32;
        #pragma unroll
        for (int fi = tid; fi < BN * 4; fi += 256) {
            int r = fi >> 2, sg = fi & 3;
            cp_async16(sm_u + (uint32_t)(st * STG + ASTG + r * AW + sg * 4) * 4,
                       Wc + (size_t)r * K + sg * 8);
        }
    };

    #pragma unroll
    for (int p = 0; p < NSTAGE - 1; ++p) {
        if (p < nch) load_chunk(p, p);
        CP_COMMIT();
    }

    for (int c = 0; c < nch; ++c) {
        asm volatile("cp.async.wait_group %0;" :: "n"(NSTAGE - 2) : "memory");
        __syncthreads();
        int nx = c + NSTAGE - 1;
        if (nx < nch) load_chunk(nx, nx % NSTAGE);
        CP_COMMIT();
        const uint32_t stOff = (uint32_t)((c % NSTAGE) * STG * 4);
        #pragma unroll
        for (int ks = 0; ks < 2; ++ks) {
            uint32_t a[2][4], b[NT][2];
            #pragma unroll
            for (int mt = 0; mt < 2; ++mt)
                ldsm_x4(a[mt], aLM + stOff + (uint32_t)(mt * 16 * AW * 4 + ks * 32));
            if (NT == 1) {
                ldsm_x2(b[0], bLM2 + stOff + (uint32_t)(ks * 32));
            } else {
                #pragma unroll
                for (int p = 0; p < NT / 2; ++p) {
                    uint32_t t4[4];
                    ldsm_x4(t4, bLM4 + stOff + (uint32_t)(p * 16 * AW * 4 + ks * 32));
                    b[2*p][0] = t4[0]; b[2*p][1] = t4[1];
                    b[2*p+1][0] = t4[2]; b[2*p+1][1] = t4[3];
                }
            }
            #pragma unroll
            for (int mt = 0; mt < 2; ++mt)
                #pragma unroll
                for (int nt = 0; nt < NT; ++nt)
                    mma_bf16(acc[mt][nt], a[mt], b[nt]);
        }
    }
    __syncthreads();

    #pragma unroll
    for (int mt = 0; mt < 2; ++mt) {
        int r0 = bm + warpM * 32 + mt * 16 + quad;
        #pragma unroll
        for (int nt = 0; nt < NT; ++nt) {
            int gc = bn + warpN * WN + nt * 8 + qk * 2;
            #pragma unroll
            for (int half = 0; half < 2; ++half) {
                int row = r0 + half * 8;
                float v0 = acc[mt][nt][half * 2 + 0];
                float v1 = acc[mt][nt][half * 2 + 1];
                size_t gi = (size_t)row * ldc + gc;
                if (OUTMODE == 2) {
                    bf16* C = (bf16*)Cv;
                    if (gc < N_store) C[gi] = __float2bfloat16(v0);
                    if (gc + 1 < N_store) C[gi + 1] = __float2bfloat16(v1);
                } else {
                    float* C = (float*)Cv;
                    if (gc < N_store) {
                        if (OUTMODE == 1) v0 += C[gi];
                        C[gi] = v0;
                    }
                    if (gc + 1 < N_store) {
                        if (OUTMODE == 1) v1 += C[gi + 1];
                        C[gi + 1] = v1;
                    }
                }
            }
        }
    }
}

// -------- rmsnorm: warp per token, bf16 out --------
__global__ void rmsnorm_kernel(const float* __restrict__ x, const float* __restrict__ w,
                               bf16* __restrict__ o, int ldo) {
    int tok = (blockIdx.x * blockDim.x + threadIdx.x) >> 5;
    int lane = threadIdx.x & 31;
    if (tok >= NTOK) return;
    const float* xr = x + (size_t)tok * D_MODEL;
    float ss = 0.f;
    for (int i = lane; i < D_MODEL; i += 32) { float v = xr[i]; ss += v * v; }
    #pragma unroll
    for (int off = 16; off; off >>= 1) ss += __shfl_xor_sync(~0u, ss, off);
    float inv = rsqrtf(ss * (1.f / D_MODEL) + EPS);
    for (int i = lane; i < D_MODEL; i += 32)
        o[(size_t)tok * ldo + i] = __float2bfloat16(xr[i] * inv * w[i]);
}

__global__ void final_kernel(const float* __restrict__ f, const float* __restrict__ x,
                             const float* __restrict__ w, float* __restrict__ o) {
    int tok = (blockIdx.x * blockDim.x + threadIdx.x) >> 5;
    int lane = threadIdx.x & 31;
    if (tok >= NTOK) return;
    const float* xr = x + (size_t)tok * D_MODEL;
    float ss = 0.f;
    for (int i = lane; i < D_MODEL; i += 32) { float v = xr[i]; ss += v * v; }
    #pragma unroll
    for (int off = 16; off; off >>= 1) ss += __shfl_xor_sync(~0u, ss, off);
    float inv = rsqrtf(ss * (1.f / D_MODEL) + EPS);
    for (int i = lane; i < D_MODEL; i += 32)
        o[(size_t)tok * D_MODEL + i] = f[(size_t)tok * D_MODEL + i] + xr[i] * inv * w[i];
}

// -------- conv(k=4, causal) + silu: register window over 16-token tiles --------
#define CLT 16
__global__ void conv_silu_kernel(const bf16* __restrict__ xz, const float* __restrict__ cw,
                                 const float* __restrict__ cb, bf16* __restrict__ xc) {
    int d = blockIdx.x * 128 + threadIdx.x;
    if (d >= D_INNER) return;
    int l0 = blockIdx.y * CLT, b = blockIdx.z;
    float w0 = cw[d * 4 + 0], w1 = cw[d * 4 + 1], w2 = cw[d * 4 + 2], w3 = cw[d * 4 + 3];
    float bb = cb[d];
    size_t row = (size_t)b * L_SEQ + l0;
    const bf16* src = xz + row * TWO_DI + d;
    bf16* dst = xc + row * KI + d;
    float x0, x1, x2;
    if (l0 == 0) { x0 = x1 = x2 = 0.f; }
    else {
        x0 = __bfloat162float(src[-3 * TWO_DI]);
        x1 = __bfloat162float(src[-2 * TWO_DI]);
        x2 = __bfloat162float(src[-1 * TWO_DI]);
    }
    #pragma unroll
    for (int i = 0; i < CLT; ++i) {
        float x3 = __bfloat162float(src[(size_t)i * TWO_DI]);
        float acc = bb + w0 * x0 + w1 * x1 + w2 * x2 + w3 * x3;
        dst[(size_t)i * KI] = __float2bfloat16(acc / (1.f + __expf(-acc)));
        x0 = x1; x1 = x2; x2 = x3;
    }
}

// -------- chunked selective scan (single serial pass + parallel fixup) ----
__device__ __forceinline__ float softplus_f(float a) {
    return (a > 15.f) ? a : log1pf(__expf(a));
}
__device__ __forceinline__ bool a_is_arange(const float* Av) {
    bool ok = Av[0] < 0.f;
    #pragma unroll
    for (int s = 1; s < 16; ++s)
        ok = ok && (fabsf(Av[s] - (float)(s + 1) * Av[0]) <= 1e-4f * fabsf(Av[s]));
    return ok;
}

// scanA: serial pass with h0=0. Emits yloc(+u*D), chunk summary Lc + sum(dt).
__global__ __launch_bounds__(128) void scanA_kernel(
    const bf16* __restrict__ u, const float* __restrict__ xdbl,
    const float* __restrict__ A_log, const float* __restrict__ dtw,
    const float* __restrict__ dtb, const float* __restrict__ Dp,
    float* __restrict__ Lc, float* __restrict__ sdtc, bf16* __restrict__ yloc) {
    __shared__ float sDL[SCT][18];
    __shared__ float sB[SCT][16];
    __shared__ float sC[SCT][16];
    __shared__ bf16 s_u[SCT][128];
    int b = blockIdx.z, c = blockIdx.y, d0 = blockIdx.x * 128;
    int tid = threadIdx.x;
    int d = d0 + tid;
    bool act = d < D_INNER;
    int dc = act ? d : (D_INNER - 1);
    size_t rb = (size_t)b * L_SEQ + (size_t)c * SCT;
    float Av[16];
    #pragma unroll
    for (int s = 0; s < 16; s += 4) {
        float4 al = *(const float4*)(A_log + (size_t)dc * 16 + s);
        Av[s + 0] = -__expf(al.x); Av[s + 1] = -__expf(al.y);
        Av[s + 2] = -__expf(al.z); Av[s + 3] = -__expf(al.w);
    }
    const bool fast = a_is_arange(Av);
    const float Av0 = Av[0];
    float wv[DT_RANK];
    #pragma unroll
    for (int r = 0; r < DT_RANK; ++r) wv[r] = dtw[(size_t)dc * DT_RANK + r];
    float bias = dtb[dc];
    float Dv = Dp[dc];
    for (int i = tid; i < SCT * 16; i += 128) {
        int t = i >> 4, s = i & 15;
        const float* g = xdbl + (rb + t) * XW + DT_RANK;
        sB[t][s] = g[s];
        sC[t][s] = g[16 + s];
    }
    for (int i = tid; i < SCT * DT_RANK; i += 128) {
        int t = i / DT_RANK, r = i - t * DT_RANK;
        sDL[t][r] = xdbl[(rb + t) * XW + r];
    }
    for (int q = tid; q < SCT * 64; q += 128) {
        int tt = q >> 6, dp = (q & 63) * 2;
        *(uint32_t*)&s_u[tt][dp] = *(const uint32_t*)(u + (rb + tt) * KI + d0 + dp);
    }
    __syncthreads();
    float h[16];
    #pragma unroll
    for (int s = 0; s < 16; ++s) h[s] = 0.f;
    float sd = 0.f;
    #pragma unroll 4
    for (int t = 0; t < SCT; ++t) {
        float dta = bias;
        const float* dl = sDL[t];
        #pragma unroll
        for (int r = 0; r < DT_RANK; ++r) dta = fmaf(dl[r], wv[r], dta);
        float dtv = softplus_f(dta);
        float uv = __bfloat162float(s_u[t][tid]);
        float e = dtv * uv;
        sd += dtv;
        const float4* pB = (const float4*)sB[t];
        const float4* pC = (const float4*)sC[t];
        float y = 0.f;
        if (fast) {
            float q = __expf(dtv * Av0);
            float p = 1.f;
            #pragma unroll
            for (int s4 = 0; s4 < 4; ++s4) {
                float4 Bv = pB[s4];
                float4 Cv = pC[s4];
                p *= q; h[s4*4+0] = fmaf(p, h[s4*4+0], e * Bv.x);
                p *= q; h[s4*4+1] = fmaf(p, h[s4*4+1], e * Bv.y);
                p *= q; h[s4*4+2] = fmaf(p, h[s4*4+2], e * Bv.z);
                p *= q; h[s4*4+3] = fmaf(p, h[s4*4+3], e * Bv.w);
                y += h[s4*4+0] * Cv.x + h[s4*4+1] * Cv.y
                   + h[s4*4+2] * Cv.z + h[s4*4+3] * Cv.w;
            }
        } else {
            #pragma unroll
            for (int s4 = 0; s4 < 4; ++s4) {
                float4 Bv = pB[s4];
                float4 Cv = pC[s4];
                h[s4*4+0] = fmaf(__expf(dtv * Av[s4*4+0]), h[s4*4+0], e * Bv.x);
                h[s4*4+1] = fmaf(__expf(dtv * Av[s4*4+1]), h[s4*4+1], e * Bv.y);
                h[s4*4+2] = fmaf(__expf(dtv * Av[s4*4+2]), h[s4*4+2], e * Bv.z);
                h[s4*4+3] = fmaf(__expf(dtv * Av[s4*4+3]), h[s4*4+3], e * Bv.w);
                y += h[s4*4+0] * Cv.x + h[s4*4+1] * Cv.y
                   + h[s4*4+2] * Cv.z + h[s4*4+3] * Cv.w;
            }
        }
        if (act)
            yloc[(rb + t) * KI + d] = __float2bfloat16(y + uv * Dv);
    }
    if (act) {
        size_t o = ((size_t)b * NCHK + c) * D_INNER + d;
        float4* pL = (float4*)(Lc + o * 16);
        #pragma unroll
        for (int s4 = 0; s4 < 4; ++s4)
            pL[s4] = make_float4(h[s4*4+0], h[s4*4+1], h[s4*4+2], h[s4*4+3]);
        sdtc[o] = sd;
    }
}

// scan2: stitch chunk summaries -> initial state per chunk
__global__ void scan2_kernel(const float* __restrict__ Lc, const float* __restrict__ sdtc,
                             const float* __restrict__ A_log, float* __restrict__ H0) {
    int idx = blockIdx.x * 128 + threadIdx.x;
    if (idx >= B_SZ * D_INNER * D_STATE) return;
    int s = idx & 15, rest = idx >> 4;
    int d = rest % D_INNER, b = rest / D_INNER;
    float Av = -__expf(A_log[(size_t)d * 16 + s]);
    float h = 0.f;
    #pragma unroll 8
    for (int c = 0; c < NCHK; ++c) {
        size_t o = (((size_t)b * NCHK + c) * D_INNER + d);
        H0[o * 16 + s] = h;
        h = __expf(Av * sdtc[o]) * h + Lc[o * 16 + s];
    }
}

// scanC: fixup: y = yloc + C·(P(cumdt)·H0); cumdt recomputed inline; gate.
__global__ __launch_bounds__(128) void scanC_kernel(
    const float* __restrict__ xdbl, const bf16* __restrict__ xz,
    const float* __restrict__ A_log, const float* __restrict__ dtw,
    const float* __restrict__ dtb, const float* __restrict__ H0,
    bf16* __restrict__ y2) {
    __shared__ float sDL[SCT][18];
    __shared__ float sC[SCT][16];
    int b = blockIdx.z, c = blockIdx.y, d0 = blockIdx.x * 128;
    int tid = threadIdx.x;
    int d = d0 + tid;
    bool act = d < D_INNER;
    int dc = act ? d : (D_INNER - 1);
    size_t rb = (size_t)b * L_SEQ + (size_t)c * SCT;
    float Av[16];
    #pragma unroll
    for (int s = 0; s < 16; s += 4) {
        float4 al = *(const float4*)(A_log + (size_t)dc * 16 + s);
        Av[s + 0] = -__expf(al.x); Av[s + 1] = -__expf(al.y);
        Av[s + 2] = -__expf(al.z); Av[s + 3] = -__expf(al.w);
    }
    const bool fast = a_is_arange(Av);
    const float Av0 = Av[0];
    float wv[DT_RANK];
    #pragma unroll
    for (int r = 0; r < DT_RANK; ++r) wv[r] = dtw[(size_t)dc * DT_RANK + r];
    float bias = dtb[dc];
    float h0[16];
    {
        size_t o = ((size_t)b * NCHK + c) * D_INNER + dc;
        const float4* pH = (const float4*)(H0 + o * 16);
        #pragma unroll
        for (int s4 = 0; s4 < 4; ++s4) {
            float4 hv = pH[s4];
            h0[s4*4+0] = hv.x; h0[s4*4+1] = hv.y; h0[s4*4+2] = hv.z; h0[s4*4+3] = hv.w;
        }
    }
    for (int i = tid; i < SCT * 16; i += 128) {
        int t = i >> 4, s = i & 15;
        sC[t][s] = xdbl[(rb + t) * XW + DT_RANK + 16 + s];
    }
    for (int i = tid; i < SCT * DT_RANK; i += 128) {
        int t = i / DT_RANK, r = i - t * DT_RANK;
        sDL[t][r] = xdbl[(rb + t) * XW + r];
    }
    __syncthreads();
    float sd = 0.f;
    #pragma unroll 4
    for (int t = 0; t < SCT; ++t) {
        float dta = bias;
        const float* dl = sDL[t];
        #pragma unroll
        for (int r = 0; r < DT_RANK; ++r) dta = fmaf(dl[r], wv[r], dta);
        sd += softplus_f(dta);
        size_t gi = (rb + t) * KI + (size_t)dc;
        float yl = __bfloat162float(y2[gi]);
        float z = __bfloat162float(xz[(rb + t) * TWO_DI + D_INNER + dc]);
        const float* Cv = sC[t];
        float corr = 0.f;
        if (fast) {
            float q = __expf(sd * Av0);
            float p = 1.f;
            #pragma unroll
            for (int s = 0; s < 16; ++s) {
                p *= q;
                corr = fmaf(p * h0[s], Cv[s], corr);
            }
        } else {
            #pragma unroll
            for (int s = 0; s < 16; ++s)
                corr = fmaf(__expf(sd * Av[s]) * h0[s], Cv[s], corr);
        }
        if (act) {
            float y = yl + corr;
            y2[gi] = __float2bfloat16(y * (z / (1.f + __expf(-z))));
        }
    }
}

// -------- weight packing --------
__global__ void pack1_kernel(const float* __restrict__ ipw, bf16* __restrict__ win) {
    int i = blockIdx.x * 256 + threadIdx.x;
    int total = N_LAYERS * 1032 * 258;
    if (i >= total) return;
    int k = i % 258, nr = i / 258, n = nr % 1032, l = nr / 1032;
    win[((size_t)l * WIN_R + n) * KM + k] = __float2bfloat16(ipw[i]);
}
__global__ void pack2_kernel(const float* __restrict__ opw, const float* __restrict__ xpw,
                             bf16* __restrict__ wout, bf16* __restrict__ wxp) {
    int i = blockIdx.x * 256 + threadIdx.x;
    const int OUT_T = N_LAYERS * 258 * 516, XP_T = N_LAYERS * 49 * 516;
    if (i < OUT_T) {
        int k = i % 516, nr = i / 516, n = nr % 258, l = nr / 258;
        wout[((size_t)l * WOUT_R + n) * KI + k] = __float2bfloat16(opw[i]);
    } else if (i < OUT_T + XP_T) {
        int j = i - OUT_T;
        int k = j % 516, nr = j / 516, n = nr % 49, l = nr / 49;
        wxp[((size_t)l * WXP_R + n) * KI + k] = __float2bfloat16(xpw[j]);
    }
}

// -------- host --------
extern "C" void kernel_launch(void* const* d_in, const int* in_sizes, int n_in,
                              void* d_out, int out_size) {
    const float* fuse  = (const float*)d_in[0];
    const float* nwv   = (const float*)d_in[1];
    const float* ipw   = (const float*)d_in[2];
    const float* cwv   = (const float*)d_in[3];
    const float* cbv   = (const float*)d_in[4];
    const float* xpw   = (const float*)d_in[5];
    const float* dtwv  = (const float*)d_in[6];
    const float* dtbv  = (const float*)d_in[7];
    const float* Alv   = (const float*)d_in[8];
    const float* Dpv   = (const float*)d_in[9];
    const float* opw   = (const float*)d_in[10];
    const float* fw    = (const float*)d_in[11];
    float* out = (float*)d_out;

    float *p_x, *p_xdbl, *p_L, *p_H0, *p_sdt;
    bf16 *p_xn, *p_xz, *p_xc, *p_y2, *p_win, *p_wout, *p_wxp;
    cudaGetSymbolAddress((void**)&p_x, g_x);
    cudaGetSymbolAddress((void**)&p_xn, g_xn);
    cudaGetSymbolAddress((void**)&p_xz, g_xz);
    cudaGetSymbolAddress((void**)&p_xc, g_xc);
    cudaGetSymbolAddress((void**)&p_xdbl, g_xdbl);
    cudaGetSymbolAddress((void**)&p_y2, g_y2);
    cudaGetSymbolAddress((void**)&p_win, g_win);
    cudaGetSymbolAddress((void**)&p_wout, g_wout);
    cudaGetSymbolAddress((void**)&p_wxp, g_wxp);
    cudaGetSymbolAddress((void**)&p_L, g_L);
    cudaGetSymbolAddress((void**)&p_H0, g_H0);
    cudaGetSymbolAddress((void**)&p_sdt, g_sdt);

    // smem sizes: NSTAGE * (BM+BN) * AW * 4 bytes
    const int SM_IN  = 3 * (64 + 128) * AW * 4;   // 46080
    const int SM_OUT = 3 * (64 + 64) * AW * 4;    // 30720
    const int SM_XP  = 3 * (32 + 64) * AW * 4;    // 23040
    cudaFuncSetAttribute((const void*)gemm_bf16<64, 128, 2, 3>,
                         cudaFuncAttributeMaxDynamicSharedMemorySize, SM_IN);

    pack1_kernel<<<(N_LAYERS * 1032 * 258 + 255) / 256, 256>>>(ipw, p_win);
    {
        int tot = N_LAYERS * 258 * 516 + N_LAYERS * 49 * 516;
        pack2_kernel<<<(tot + 255) / 256, 256>>>(opw, xpw, p_wout, p_wxp);
    }
    cudaMemcpyAsync(p_x, fuse, (size_t)NTOK * D_MODEL * sizeof(float),
                    cudaMemcpyDeviceToDevice);

    for (int l = 0; l < N_LAYERS; ++l) {
        const float* Al = Alv + (size_t)l * D_INNER * 16;
        const float* dtw = dtwv + (size_t)l * D_INNER * DT_RANK;
        const float* dtb = dtbv + (size_t)l * D_INNER;
        rmsnorm_kernel<<<NTOK / 8, 256>>>(p_x, nwv + (size_t)l * D_MODEL, p_xn, KM);
        gemm_bf16<64, 128, 2, 3><<<dim3(9, 128), 256, SM_IN>>>(
            p_xn, p_win + (size_t)l * WIN_R * KM, p_xz, TWO_DI, KM, KM, TWO_DI);
        conv_silu_kernel<<<dim3(5, L_SEQ / CLT, B_SZ), 128>>>(
            p_xz, cwv + (size_t)l * D_INNER * 4, cbv + (size_t)l * D_INNER, p_xc);
        gemm_bf16<32, 64, 0, 3><<<dim3(1, 256), 256, SM_XP>>>(
            p_xc, p_wxp + (size_t)l * WXP_R * KI, p_xdbl, 49, KI, KI, XW);
        scanA_kernel<<<dim3(5, NCHK, B_SZ), 128>>>(
            p_xc, p_xdbl, Al, dtw, dtb, Dpv + (size_t)l * D_INNER, p_L, p_sdt, p_y2);
        scan2_kernel<<<(B_SZ * D_INNER * D_STATE + 127) / 128, 128>>>(
            p_L, p_sdt, Al, p_H0);
        scanC_kernel<<<dim3(5, NCHK, B_SZ), 128>>>(
            p_xdbl, p_xz, Al, dtw, dtb, p_H0, p_y2);
        gemm_bf16<64, 64, 1, 3><<<dim3(5, 128), 256, SM_OUT>>>(
            p_y2, p_wout + (size_t)l * WOUT_R * KI, p_x, D_MODEL, KI, KI, D_MODEL);
    }
    final_kernel<<<NTOK / 8, 256>>>(fuse, p_x, fw, out);
    (void)in_sizes; (void)n_in; (void)out_size;
}

// round 15
// speedup vs baseline: 1.0001x; 1.0001x over previous
#include <cuda_runtime.h>
#include <cuda_bf16.h>
#include <math.h>
#include <stdint.h>

#define B_SZ 4
#define L_SEQ 2048
#define D_MODEL 258
#define N_LAYERS 4
#define D_STATE 16
#define D_INNER 516
#define DT_RANK 17
#define TWO_DI 1032
#define XW 56            // padded xdbl stride (49 real cols)
#define NTOK 8192
#define EPS 1e-5f
#define KM 288           // 258 padded to 32-chunks
#define KI 544           // 516 padded
#define WIN_R 1152       // 9 * 128
#define WOUT_R 320       // 5 * 64
#define WXP_R 64
#define NCHK 128         // scan chunks
#define SCT 16           // tokens per scan chunk
#define STH 132          // scan threads per block (4 blocks x 132 = 528 >= 516)

typedef __nv_bfloat16 bf16;

// -------- device scratch (zero-init; +pad for vectorized edge reads) --------
__device__ __align__(256) float g_x[NTOK * D_MODEL];
__device__ __align__(256) bf16  g_xn[NTOK * KM];
__device__ __align__(256) bf16  g_xz[NTOK * TWO_DI + 256];
__device__ __align__(256) bf16  g_xc[NTOK * KI + 256];
__device__ __align__(256) float g_xdbl[NTOK * XW];
__device__ __align__(256) bf16  g_y2[NTOK * KI + 256];
__device__ __align__(256) float g_cum[NTOK * KI + 256];
__device__ __align__(256) bf16  g_win[N_LAYERS * WIN_R * KM];
__device__ __align__(256) bf16  g_wout[N_LAYERS * WOUT_R * KI];
__device__ __align__(256) bf16  g_wxp[N_LAYERS * WXP_R * KI];
__device__ __align__(256) float g_L[B_SZ * NCHK * D_INNER * D_STATE];
__device__ __align__(256) float g_H0[B_SZ * NCHK * D_INNER * D_STATE];
__device__ __align__(256) float g_sdt[B_SZ * NCHK * D_INNER];

// -------- helpers --------
__device__ __forceinline__ uint32_t smem_u32(const void* p) {
    uint32_t a;
    asm("{ .reg .u64 t; cvta.to.shared.u64 t, %1; cvt.u32.u64 %0, t; }" : "=r"(a) : "l"(p));
    return a;
}
__device__ __forceinline__ void cp_async16(uint32_t dst, const void* src) {
    asm volatile("cp.async.cg.shared.global [%0], [%1], 16;" :: "r"(dst), "l"(src));
}
#define CP_COMMIT() asm volatile("cp.async.commit_group;" ::: "memory")

__device__ __forceinline__ void mma_bf16(float* d, const uint32_t* a, const uint32_t* b) {
    asm volatile(
        "mma.sync.aligned.m16n8k16.row.col.f32.bf16.bf16.f32 "
        "{%0,%1,%2,%3},{%4,%5,%6,%7},{%8,%9},{%0,%1,%2,%3};"
        : "+f"(d[0]), "+f"(d[1]), "+f"(d[2]), "+f"(d[3])
        : "r"(a[0]), "r"(a[1]), "r"(a[2]), "r"(a[3]), "r"(b[0]), "r"(b[1]));
}
__device__ __forceinline__ void ldsm_x4(uint32_t* r, uint32_t addr) {
    asm volatile("ldmatrix.sync.aligned.m8n8.x4.shared.b16 {%0,%1,%2,%3}, [%4];"
        : "=r"(r[0]), "=r"(r[1]), "=r"(r[2]), "=r"(r[3]) : "r"(addr));
}
__device__ __forceinline__ void ldsm_x2(uint32_t* r, uint32_t addr) {
    asm volatile("ldmatrix.sync.aligned.m8n8.x2.shared.b16 {%0,%1}, [%2];"
        : "=r"(r[0]), "=r"(r[1]) : "r"(addr));
}

// -------- bf16 mma GEMM: C[8192,N] = A[8192,K]bf16 @ W[N,K]bf16^T --------
#define AW 20            // smem row stride in words (40 bf16) — LDSM conflict-free
template <int BM, int BN, int OUTMODE, int NSTAGE>
__global__ __launch_bounds__(256) void gemm_bf16(
    const bf16* __restrict__ A, const bf16* __restrict__ W,
    void* __restrict__ Cv, int N_store, int K, int lda, int ldc) {
    constexpr int MW = BM / 32;
    constexpr int NW = 8 / MW;
    constexpr int WN = BN / NW;
    constexpr int NT = WN / 8;
    constexpr int ASTG = BM * AW, BSTG = BN * AW, STG = ASTG + BSTG;
    extern __shared__ uint32_t sm[];
    const int tid = threadIdx.x, wid = tid >> 5, lane = tid & 31;
    const int warpM = wid % MW, warpN = wid / MW;
    const int quad = lane >> 2, qk = lane & 3;
    const int bm = blockIdx.y * BM, bn = blockIdx.x * BN;
    float acc[2][NT][4];
    #pragma unroll
    for (int i = 0; i < 2; ++i)
        #pragma unroll
        for (int j = 0; j < NT; ++j)
            #pragma unroll
            for (int k = 0; k < 4; ++k) acc[i][j][k] = 0.f;

    const bf16* Ab = A + (size_t)bm * lda;
    const bf16* Wb = W + (size_t)bn * K;
    const int nch = K >> 5;
    const uint32_t sm_u = smem_u32(sm);
    const int l8 = lane & 7, jm = lane >> 3;

    const uint32_t aLM = sm_u +
        (uint32_t)(((warpM * 32 + ((jm & 1) << 3) + l8) * AW + ((jm >> 1) << 2)) * 4);
    const uint32_t bLM4 = sm_u + ASTG * 4 +
        (uint32_t)(((warpN * WN + ((jm >> 1) << 3) + l8) * AW + ((jm & 1) << 2)) * 4);
    const uint32_t bLM2 = sm_u + ASTG * 4 +
        (uint32_t)(((warpN * WN + l8) * AW + (((lane >> 3) & 1) << 2)) * 4);

    auto load_chunk = [&](int c, int st) {
        const bf16* Ac = Ab + c * 32;
        #pragma unroll
        for (int fi = tid; fi < BM * 4; fi += 256) {
            int r = fi >> 2, sg = fi & 3;
            cp_async16(sm_u + (uint32_t)(st * STG + r * AW + sg * 4) * 4,
                       Ac + (size_t)r * lda + sg * 8);
        }
        const bf16* Wc = Wb + c * 32;
        #pragma unroll
        for (int fi = tid; fi < BN * 4; fi += 256) {
            int r = fi >> 2, sg = fi & 3;
            cp_async16(sm_u + (uint32_t)(st * STG + ASTG + r * AW + sg * 4) * 4,
                       Wc + (size_t)r * K + sg * 8);
        }
    };

    #pragma unroll
    for (int p = 0; p < NSTAGE - 1; ++p) {
        if (p < nch) load_chunk(p, p);
        CP_COMMIT();
    }

    for (int c = 0; c < nch; ++c) {
        asm volatile("cp.async.wait_group %0;" :: "n"(NSTAGE - 2) : "memory");
        __syncthreads();
        int nx = c + NSTAGE - 1;
        if (nx < nch) load_chunk(nx, nx % NSTAGE);
        CP_COMMIT();
        const uint32_t stOff = (uint32_t)((c % NSTAGE) * STG * 4);
        #pragma unroll
        for (int ks = 0; ks < 2; ++ks) {
            uint32_t a[2][4], b[NT][2];
            #pragma unroll
            for (int mt = 0; mt < 2; ++mt)
                ldsm_x4(a[mt], aLM + stOff + (uint32_t)(mt * 16 * AW * 4 + ks * 32));
            if (NT == 1) {
                ldsm_x2(b[0], bLM2 + stOff + (uint32_t)(ks * 32));
            } else {
                #pragma unroll
                for (int p = 0; p < NT / 2; ++p) {
                    uint32_t t4[4];
                    ldsm_x4(t4, bLM4 + stOff + (uint32_t)(p * 16 * AW * 4 + ks * 32));
                    b[2*p][0] = t4[0]; b[2*p][1] = t4[1];
                    b[2*p+1][0] = t4[2]; b[2*p+1][1] = t4[3];
                }
            }
            #pragma unroll
            for (int mt = 0; mt < 2; ++mt)
                #pragma unroll
                for (int nt = 0; nt < NT; ++nt)
                    mma_bf16(acc[mt][nt], a[mt], b[nt]);
        }
    }
    __syncthreads();

    #pragma unroll
    for (int mt = 0; mt < 2; ++mt) {
        int r0 = bm + warpM * 32 + mt * 16 + quad;
        #pragma unroll
        for (int nt = 0; nt < NT; ++nt) {
            int gc = bn + warpN * WN + nt * 8 + qk * 2;
            #pragma unroll
            for (int half = 0; half < 2; ++half) {
                int row = r0 + half * 8;
                float v0 = acc[mt][nt][half * 2 + 0];
                float v1 = acc[mt][nt][half * 2 + 1];
                size_t gi = (size_t)row * ldc + gc;
                if (OUTMODE == 2) {
                    bf16* C = (bf16*)Cv;
                    if (gc < N_store) C[gi] = __float2bfloat16(v0);
                    if (gc + 1 < N_store) C[gi + 1] = __float2bfloat16(v1);
                } else {
                    float* C = (float*)Cv;
                    if (gc < N_store) {
                        if (OUTMODE == 1) v0 += C[gi];
                        C[gi] = v0;
                    }
                    if (gc + 1 < N_store) {
                        if (OUTMODE == 1) v1 += C[gi + 1];
                        C[gi + 1] = v1;
                    }
                }
            }
        }
    }
}

// -------- rmsnorm: warp per token, bf16 out --------
__global__ void rmsnorm_kernel(const float* __restrict__ x, const float* __restrict__ w,
                               bf16* __restrict__ o, int ldo) {
    int tok = (blockIdx.x * blockDim.x + threadIdx.x) >> 5;
    int lane = threadIdx.x & 31;
    if (tok >= NTOK) return;
    const float* xr = x + (size_t)tok * D_MODEL;
    float ss = 0.f;
    for (int i = lane; i < D_MODEL; i += 32) { float v = xr[i]; ss += v * v; }
    #pragma unroll
    for (int off = 16; off; off >>= 1) ss += __shfl_xor_sync(~0u, ss, off);
    float inv = rsqrtf(ss * (1.f / D_MODEL) + EPS);
    for (int i = lane; i < D_MODEL; i += 32)
        o[(size_t)tok * ldo + i] = __float2bfloat16(xr[i] * inv * w[i]);
}

__global__ void final_kernel(const float* __restrict__ f, const float* __restrict__ x,
                             const float* __restrict__ w, float* __restrict__ o) {
    int tok = (blockIdx.x * blockDim.x + threadIdx.x) >> 5;
    int lane = threadIdx.x & 31;
    if (tok >= NTOK) return;
    const float* xr = x + (size_t)tok * D_MODEL;
    float ss = 0.f;
    for (int i = lane; i < D_MODEL; i += 32) { float v = xr[i]; ss += v * v; }
    #pragma unroll
    for (int off = 16; off; off >>= 1) ss += __shfl_xor_sync(~0u, ss, off);
    float inv = rsqrtf(ss * (1.f / D_MODEL) + EPS);
    for (int i = lane; i < D_MODEL; i += 32)
        o[(size_t)tok * D_MODEL + i] = f[(size_t)tok * D_MODEL + i] + xr[i] * inv * w[i];
}

// -------- conv(k=4, causal) + silu: register window over 8-token tiles --------
#define CLT 8
__global__ void conv_silu_kernel(const bf16* __restrict__ xz, const float* __restrict__ cw,
                                 const float* __restrict__ cb, bf16* __restrict__ xc) {
    int d = blockIdx.x * 128 + threadIdx.x;
    if (d >= D_INNER) return;
    int l0 = blockIdx.y * CLT, b = blockIdx.z;
    float w0 = cw[d * 4 + 0], w1 = cw[d * 4 + 1], w2 = cw[d * 4 + 2], w3 = cw[d * 4 + 3];
    float bb = cb[d];
    size_t row = (size_t)b * L_SEQ + l0;
    const bf16* src = xz + row * TWO_DI + d;
    bf16* dst = xc + row * KI + d;
    float x0, x1, x2;
    if (l0 == 0) { x0 = x1 = x2 = 0.f; }
    else {
        x0 = __bfloat162float(src[-3 * TWO_DI]);
        x1 = __bfloat162float(src[-2 * TWO_DI]);
        x2 = __bfloat162float(src[-1 * TWO_DI]);
    }
    #pragma unroll
    for (int i = 0; i < CLT; ++i) {
        float x3 = __bfloat162float(src[(size_t)i * TWO_DI]);
        float acc = bb + w0 * x0 + w1 * x1 + w2 * x2 + w3 * x3;
        dst[(size_t)i * KI] = __float2bfloat16(acc / (1.f + __expf(-acc)));
        x0 = x1; x1 = x2; x2 = x3;
    }
}

// -------- chunked selective scan (single serial pass + parallel fixup) ----
__device__ __forceinline__ float softplus_f(float a) {
    return (a > 15.f) ? a : log1pf(__expf(a));
}
__device__ __forceinline__ bool a_is_arange(const float* Av) {
    bool ok = Av[0] < 0.f;
    #pragma unroll
    for (int s = 1; s < 16; ++s)
        ok = ok && (fabsf(Av[s] - (float)(s + 1) * Av[0]) <= 1e-4f * fabsf(Av[s]));
    return ok;
}

// scanA: serial pass, h0=0. Emits yloc(+u*D), cumdt, chunk summary Lc + sum(dt).
__global__ __launch_bounds__(STH) void scanA_kernel(
    const bf16* __restrict__ u, const float* __restrict__ xdbl,
    const float* __restrict__ A_log, const float* __restrict__ dtw,
    const float* __restrict__ dtb, const float* __restrict__ Dp,
    float* __restrict__ Lc, float* __restrict__ sdtc,
    bf16* __restrict__ yloc, float* __restrict__ cum) {
    __shared__ float sDL[SCT][18];
    __shared__ float sB[SCT][16];
    __shared__ float sC[SCT][16];
    __shared__ bf16 s_u[SCT][STH];
    int b = blockIdx.z, c = blockIdx.y, d0 = blockIdx.x * STH;
    int tid = threadIdx.x;
    int d = d0 + tid;
    bool act = d < D_INNER;
    int dc = act ? d : (D_INNER - 1);
    size_t rb = (size_t)b * L_SEQ + (size_t)c * SCT;
    float Av[16];
    #pragma unroll
    for (int s = 0; s < 16; s += 4) {
        float4 al = *(const float4*)(A_log + (size_t)dc * 16 + s);
        Av[s + 0] = -__expf(al.x); Av[s + 1] = -__expf(al.y);
        Av[s + 2] = -__expf(al.z); Av[s + 3] = -__expf(al.w);
    }
    const bool fast = a_is_arange(Av);
    const float Av0 = Av[0];
    float wv[DT_RANK];
    #pragma unroll
    for (int r = 0; r < DT_RANK; ++r) wv[r] = dtw[(size_t)dc * DT_RANK + r];
    float bias = dtb[dc];
    float Dv = Dp[dc];
    for (int i = tid; i < SCT * 16; i += STH) {
        int t = i >> 4, s = i & 15;
        const float* g = xdbl + (rb + t) * XW + DT_RANK;
        sB[t][s] = g[s];
        sC[t][s] = g[16 + s];
    }
    for (int i = tid; i < SCT * DT_RANK; i += STH) {
        int t = i / DT_RANK, r = i - t * DT_RANK;
        sDL[t][r] = xdbl[(rb + t) * XW + r];
    }
    for (int q = tid; q < SCT * (STH / 2); q += STH) {
        int tt = q / (STH / 2), dp = (q % (STH / 2)) * 2;
        *(uint32_t*)&s_u[tt][dp] = *(const uint32_t*)(u + (rb + tt) * KI + d0 + dp);
    }
    __syncthreads();
    float h[16];
    #pragma unroll
    for (int s = 0; s < 16; ++s) h[s] = 0.f;
    float sd = 0.f;
    #pragma unroll 4
    for (int t = 0; t < SCT; ++t) {
        float dta = bias;
        const float* dl = sDL[t];
        #pragma unroll
        for (int r = 0; r < DT_RANK; ++r) dta = fmaf(dl[r], wv[r], dta);
        float dtv = softplus_f(dta);
        float uv = __bfloat162float(s_u[t][tid]);
        float e = dtv * uv;
        sd += dtv;
        const float4* pB = (const float4*)sB[t];
        const float4* pC = (const float4*)sC[t];
        float y = 0.f;
        if (fast) {
            float q = __expf(dtv * Av0);
            float p = 1.f;
            #pragma unroll
            for (int s4 = 0; s4 < 4; ++s4) {
                float4 Bv = pB[s4];
                float4 Cv = pC[s4];
                p *= q; h[s4*4+0] = fmaf(p, h[s4*4+0], e * Bv.x);
                p *= q; h[s4*4+1] = fmaf(p, h[s4*4+1], e * Bv.y);
                p *= q; h[s4*4+2] = fmaf(p, h[s4*4+2], e * Bv.z);
                p *= q; h[s4*4+3] = fmaf(p, h[s4*4+3], e * Bv.w);
                y += h[s4*4+0] * Cv.x + h[s4*4+1] * Cv.y
                   + h[s4*4+2] * Cv.z + h[s4*4+3] * Cv.w;
            }
        } else {
            #pragma unroll
            for (int s4 = 0; s4 < 4; ++s4) {
                float4 Bv = pB[s4];
                float4 Cv = pC[s4];
                h[s4*4+0] = fmaf(__expf(dtv * Av[s4*4+0]), h[s4*4+0], e * Bv.x);
                h[s4*4+1] = fmaf(__expf(dtv * Av[s4*4+1]), h[s4*4+1], e * Bv.y);
                h[s4*4+2] = fmaf(__expf(dtv * Av[s4*4+2]), h[s4*4+2], e * Bv.z);
                h[s4*4+3] = fmaf(__expf(dtv * Av[s4*4+3]), h[s4*4+3], e * Bv.w);
                y += h[s4*4+0] * Cv.x + h[s4*4+1] * Cv.y
                   + h[s4*4+2] * Cv.z + h[s4*4+3] * Cv.w;
            }
        }
        if (act) {
            yloc[(rb + t) * KI + d] = __float2bfloat16(y + uv * Dv);
            cum[(rb + t) * KI + d] = sd;
        }
    }
    if (act) {
        size_t o = ((size_t)b * NCHK + c) * D_INNER + d;
        float4* pL = (float4*)(Lc + o * 16);
        #pragma unroll
        for (int s4 = 0; s4 < 4; ++s4)
            pL[s4] = make_float4(h[s4*4+0], h[s4*4+1], h[s4*4+2], h[s4*4+3]);
        sdtc[o] = sd;
    }
}

// scan2: stitch chunk summaries -> initial state per chunk
__global__ void scan2_kernel(const float* __restrict__ Lc, const float* __restrict__ sdtc,
                             const float* __restrict__ A_log, float* __restrict__ H0) {
    int idx = blockIdx.x * 128 + threadIdx.x;
    if (idx >= B_SZ * D_INNER * D_STATE) return;
    int s = idx & 15, rest = idx >> 4;
    int d = rest % D_INNER, b = rest / D_INNER;
    float Av = -__expf(A_log[(size_t)d * 16 + s]);
    float h = 0.f;
    #pragma unroll 8
    for (int c = 0; c < NCHK; ++c) {
        size_t o = (((size_t)b * NCHK + c) * D_INNER + d);
        H0[o * 16 + s] = h;
        h = __expf(Av * sdtc[o]) * h + Lc[o * 16 + s];
    }
}

// scanC: fixup: y = yloc + C·(P(cumdt)·H0); gate.
__global__ __launch_bounds__(STH) void scanC_kernel(
    const float* __restrict__ xdbl, const bf16* __restrict__ xz,
    const float* __restrict__ A_log, const float* __restrict__ H0,
    const float* __restrict__ cum, bf16* __restrict__ y2) {
    __shared__ float sC[SCT][16];
    int b = blockIdx.z, c = blockIdx.y, d0 = blockIdx.x * STH;
    int tid = threadIdx.x;
    int d = d0 + tid;
    bool act = d < D_INNER;
    int dc = act ? d : (D_INNER - 1);
    size_t rb = (size_t)b * L_SEQ + (size_t)c * SCT;
    float Av[16];
    #pragma unroll
    for (int s = 0; s < 16; s += 4) {
        float4 al = *(const float4*)(A_log + (size_t)dc * 16 + s);
        Av[s + 0] = -__expf(al.x); Av[s + 1] = -__expf(al.y);
        Av[s + 2] = -__expf(al.z); Av[s + 3] = -__expf(al.w);
    }
    const bool fast = a_is_arange(Av);
    const float Av0 = Av[0];
    float h0[16];
    {
        size_t o = ((size_t)b * NCHK + c) * D_INNER + dc;
        const float4* pH = (const float4*)(H0 + o * 16);
        #pragma unroll
        for (int s4 = 0; s4 < 4; ++s4) {
            float4 hv = pH[s4];
            h0[s4*4+0] = hv.x; h0[s4*4+1] = hv.y; h0[s4*4+2] = hv.z; h0[s4*4+3] = hv.w;
        }
    }
    for (int i = tid; i < SCT * 16; i += STH) {
        int t = i >> 4, s = i & 15;
        sC[t][s] = xdbl[(rb + t) * XW + DT_RANK + 16 + s];
    }
    __syncthreads();
    #pragma unroll 4
    for (int t = 0; t < SCT; ++t) {
        size_t gi = (rb + t) * KI + (size_t)dc;
        float cu = cum[gi];
        float yl = __bfloat162float(y2[gi]);
        float z = __bfloat162float(xz[(rb + t) * TWO_DI + D_INNER + dc]);
        const float* Cv = sC[t];
        float corr = 0.f;
        if (fast) {
            float q = __expf(cu * Av0);
            float p = 1.f;
            #pragma unroll
            for (int s = 0; s < 16; ++s) {
                p *= q;
                corr = fmaf(p * h0[s], Cv[s], corr);
            }
        } else {
            #pragma unroll
            for (int s = 0; s < 16; ++s)
                corr = fmaf(__expf(cu * Av[s]) * h0[s], Cv[s], corr);
        }
        if (act) {
            float y = yl + corr;
            y2[gi] = __float2bfloat16(y * (z / (1.f + __expf(-z))));
        }
    }
}

// -------- weight packing --------
__global__ void pack1_kernel(const float* __restrict__ ipw, bf16* __restrict__ win) {
    int i = blockIdx.x * 256 + threadIdx.x;
    int total = N_LAYERS * 1032 * 258;
    if (i >= total) return;
    int k = i % 258, nr = i / 258, n = nr % 1032, l = nr / 1032;
    win[((size_t)l * WIN_R + n) * KM + k] = __float2bfloat16(ipw[i]);
}
__global__ void pack2_kernel(const float* __restrict__ opw, const float* __restrict__ xpw,
                             bf16* __restrict__ wout, bf16* __restrict__ wxp) {
    int i = blockIdx.x * 256 + threadIdx.x;
    const int OUT_T = N_LAYERS * 258 * 516, XP_T = N_LAYERS * 49 * 516;
    if (i < OUT_T) {
        int k = i % 516, nr = i / 516, n = nr % 258, l = nr / 258;
        wout[((size_t)l * WOUT_R + n) * KI + k] = __float2bfloat16(opw[i]);
    } else if (i < OUT_T + XP_T) {
        int j = i - OUT_T;
        int k = j % 516, nr = j / 516, n = nr % 49, l = nr / 49;
        wxp[((size_t)l * WXP_R + n) * KI + k] = __float2bfloat16(xpw[j]);
    }
}

// -------- host --------
extern "C" void kernel_launch(void* const* d_in, const int* in_sizes, int n_in,
                              void* d_out, int out_size) {
    const float* fuse  = (const float*)d_in[0];
    const float* nwv   = (const float*)d_in[1];
    const float* ipw   = (const float*)d_in[2];
    const float* cwv   = (const float*)d_in[3];
    const float* cbv   = (const float*)d_in[4];
    const float* xpw   = (const float*)d_in[5];
    const float* dtwv  = (const float*)d_in[6];
    const float* dtbv  = (const float*)d_in[7];
    const float* Alv   = (const float*)d_in[8];
    const float* Dpv   = (const float*)d_in[9];
    const float* opw   = (const float*)d_in[10];
    const float* fw    = (const float*)d_in[11];
    float* out = (float*)d_out;

    float *p_x, *p_xdbl, *p_L, *p_H0, *p_sdt, *p_cum;
    bf16 *p_xn, *p_xz, *p_xc, *p_y2, *p_win, *p_wout, *p_wxp;
    cudaGetSymbolAddress((void**)&p_x, g_x);
    cudaGetSymbolAddress((void**)&p_xn, g_xn);
    cudaGetSymbolAddress((void**)&p_xz, g_xz);
    cudaGetSymbolAddress((void**)&p_xc, g_xc);
    cudaGetSymbolAddress((void**)&p_xdbl, g_xdbl);
    cudaGetSymbolAddress((void**)&p_y2, g_y2);
    cudaGetSymbolAddress((void**)&p_cum, g_cum);
    cudaGetSymbolAddress((void**)&p_win, g_win);
    cudaGetSymbolAddress((void**)&p_wout, g_wout);
    cudaGetSymbolAddress((void**)&p_wxp, g_wxp);
    cudaGetSymbolAddress((void**)&p_L, g_L);
    cudaGetSymbolAddress((void**)&p_H0, g_H0);
    cudaGetSymbolAddress((void**)&p_sdt, g_sdt);

    // smem sizes: NSTAGE * (BM+BN) * AW * 4 bytes
    const int SM_IN  = 3 * (64 + 128) * AW * 4;   // 46080
    const int SM_OUT = 3 * (64 + 64) * AW * 4;    // 30720
    const int SM_XP  = 3 * (32 + 64) * AW * 4;    // 23040
    cudaFuncSetAttribute((const void*)gemm_bf16<64, 128, 2, 3>,
                         cudaFuncAttributeMaxDynamicSharedMemorySize, SM_IN);

    pack1_kernel<<<(N_LAYERS * 1032 * 258 + 255) / 256, 256>>>(ipw, p_win);
    {
        int tot = N_LAYERS * 258 * 516 + N_LAYERS * 49 * 516;
        pack2_kernel<<<(tot + 255) / 256, 256>>>(opw, xpw, p_wout, p_wxp);
    }
    cudaMemcpyAsync(p_x, fuse, (size_t)NTOK * D_MODEL * sizeof(float),
                    cudaMemcpyDeviceToDevice);

    for (int l = 0; l < N_LAYERS; ++l) {
        const float* Al = Alv + (size_t)l * D_INNER * 16;
        const float* dtw = dtwv + (size_t)l * D_INNER * DT_RANK;
        const float* dtb = dtbv + (size_t)l * D_INNER;
        rmsnorm_kernel<<<NTOK / 8, 256>>>(p_x, nwv + (size_t)l * D_MODEL, p_xn, KM);
        gemm_bf16<64, 128, 2, 3><<<dim3(9, 128), 256, SM_IN>>>(
            p_xn, p_win + (size_t)l * WIN_R * KM, p_xz, TWO_DI, KM, KM, TWO_DI);
        conv_silu_kernel<<<dim3(5, L_SEQ / CLT, B_SZ), 128>>>(
            p_xz, cwv + (size_t)l * D_INNER * 4, cbv + (size_t)l * D_INNER, p_xc);
        gemm_bf16<32, 64, 0, 3><<<dim3(1, 256), 256, SM_XP>>>(
            p_xc, p_wxp + (size_t)l * WXP_R * KI, p_xdbl, 49, KI, KI, XW);
        scanA_kernel<<<dim3(4, NCHK, B_SZ), STH>>>(
            p_xc, p_xdbl, Al, dtw, dtb, Dpv + (size_t)l * D_INNER, p_L, p_sdt,
            p_y2, p_cum);
        scan2_kernel<<<(B_SZ * D_INNER * D_STATE + 127) / 128, 128>>>(
            p_L, p_sdt, Al, p_H0);
        scanC_kernel<<<dim3(4, NCHK, B_SZ), STH>>>(
            p_xdbl, p_xz, Al, p_H0, p_cum, p_y2);
        gemm_bf16<64, 64, 1, 3><<<dim3(5, 128), 256, SM_OUT>>>(
            p_y2, p_wout + (size_t)l * WOUT_R * KI, p_x, D_MODEL, KI, KI, D_MODEL);
    }
    final_kernel<<<NTOK / 8, 256>>>(fuse, p_x, fw, out);
    (void)in_sizes; (void)n_in; (void)out_size;
}